// round 2
// baseline (speedup 1.0000x reference)
#include <cuda_runtime.h>
#include <math.h>

#define B_     8
#define C_     64
#define H_     256
#define W_     256
#define E_     512
#define HEADS_ 8
#define HD_    64
#define PD_    32
#define P_     16
#define NCLS_  3
#define NB_    15           // n = (256-32)/16+1
#define L_     225          // n*n
#define FV_    4096         // (C/4)*16*16
#define PROWS_ 128          // B*P
#define BROWS_ 1800         // B*L
#define ROWS_  1928         // PROWS_+BROWS_

// ---------------- scratch (device globals; no allocation) ----------------
__device__ float g_pooledF[B_*16*128*128];     // pooled features [b][cg][128][128]
__device__ float g_Apatch[(size_t)PROWS_*FV_]; // pooled patch vectors (rows 0..127)
__device__ float g_emb[ROWS_*E_];              // embeddings (pre then post LN, in place)
__device__ float g_q[PROWS_*E_];
__device__ float g_kv[BROWS_*2*E_];            // per row: [k(512) | v(512)]
__device__ float g_attn[PROWS_*E_];
__device__ float g_attnp[PROWS_*E_];
__device__ float g_res[PROWS_*E_];
__device__ float g_x[PROWS_*E_];
__device__ float g_outs[PROWS_*2];
__device__ float g_sums[B_*17*3];
__device__ float g_cnt[B_*17];
__device__ float g_newv[B_*17*3];

// ---------------- pooling ----------------
__global__ void pool_features_k(const float* __restrict__ features)
{
    int idx = blockIdx.x*256 + threadIdx.x;           // 2,097,152 total
    if (idx >= B_*16*128*128) return;
    int x  = idx & 127;
    int y  = (idx >> 7) & 127;
    int cg = (idx >> 14) & 15;
    int b  = idx >> 18;
    const float* f = features + (((size_t)(b*64 + cg*4))*256 + 2*y)*256 + 2*x;
    float s = 0.f;
    #pragma unroll
    for (int c4 = 0; c4 < 4; c4++) {
        const float* fc = f + (size_t)c4*65536;
        s += fc[0] + fc[1] + fc[256] + fc[257];
    }
    g_pooledF[idx] = s * 0.0625f;
}

__global__ void pool_patches_k(const float* __restrict__ patches)
{
    int idx = blockIdx.x*256 + threadIdx.x;           // 128*4096 = 524288
    if (idx >= PROWS_*FV_) return;
    int k   = idx & 4095;
    int row = idx >> 12;
    int xx = k & 15;
    int yy = (k >> 4) & 15;
    int cg = k >> 8;
    const float* f = patches + (((size_t)row*64 + cg*4)*32 + 2*yy)*32 + 2*xx;
    float s = 0.f;
    #pragma unroll
    for (int c4 = 0; c4 < 4; c4++) {
        const float* fc = f + c4*1024;
        s += fc[0] + fc[1] + fc[32] + fc[33];
    }
    g_Apatch[(size_t)row*FV_ + k] = s * 0.0625f;
}

// Fetch A[row][k] for the embedding GEMM without materializing the block rows:
// rows 0..127 come from g_Apatch; rows 128.. are windows into g_pooledF.
__device__ __forceinline__ float fetch_A_emb(int row, int k)
{
    if (row < PROWS_) return g_Apatch[(size_t)row*FV_ + k];
    int r2 = row - PROWS_;
    int b = r2 / L_;
    int l = r2 - b*L_;
    int r = l / NB_;
    int c = l - r*NB_;
    int px = k & 15;
    int py = (k >> 4) & 15;
    int cg = k >> 8;
    return g_pooledF[(((size_t)(b*16 + cg))*128 + (r*8 + py))*128 + c*8 + px];
}

// ---------------- embedding GEMM with fused block gather ----------------
__global__ __launch_bounds__(256) void gemm_emb_k(
    const float* __restrict__ W, const float* __restrict__ bias,
    float* __restrict__ C)
{
    const int BM = 128, BN = 64, BK = 16;
    const int M = ROWS_, N = E_, K = FV_;
    __shared__ __align__(16) float As[BK][BM+4];
    __shared__ __align__(16) float Bs[BK][BN+4];
    int tid = threadIdx.x;
    int tx = tid & 15;           // n: 16*4 = 64
    int ty = tid >> 4;           // m: 16*8 = 128
    int m0 = blockIdx.y * BM;
    int n0 = blockIdx.x * BN;

    float acc[8][4];
    #pragma unroll
    for (int i = 0; i < 8; i++)
        #pragma unroll
        for (int j = 0; j < 4; j++) acc[i][j] = 0.f;

    for (int k0 = 0; k0 < K; k0 += BK) {
        #pragma unroll
        for (int u = 0; u < 8; u++) {
            int idx = tid + u*256;
            int m = idx >> 4;
            int kk = idx & 15;
            int gm = m0 + m;
            As[kk][m] = (gm < M) ? fetch_A_emb(gm, k0 + kk) : 0.f;
        }
        #pragma unroll
        for (int u = 0; u < 4; u++) {
            int idx = tid + u*256;
            int n = idx >> 4;
            int kk = idx & 15;
            Bs[kk][n] = W[(size_t)(n0 + n)*K + k0 + kk];
        }
        __syncthreads();
        #pragma unroll
        for (int kk = 0; kk < BK; kk++) {
            float4 a0 = *(const float4*)&As[kk][ty*8];
            float4 a1 = *(const float4*)&As[kk][ty*8 + 4];
            float4 b0 = *(const float4*)&Bs[kk][tx*4];
            float a[8] = {a0.x,a0.y,a0.z,a0.w,a1.x,a1.y,a1.z,a1.w};
            float bb[4] = {b0.x,b0.y,b0.z,b0.w};
            #pragma unroll
            for (int i = 0; i < 8; i++)
                #pragma unroll
                for (int j = 0; j < 4; j++)
                    acc[i][j] += a[i]*bb[j];
        }
        __syncthreads();
    }
    float4 bi = *(const float4*)&bias[n0 + tx*4];
    #pragma unroll
    for (int i = 0; i < 8; i++) {
        int m = m0 + ty*8 + i;
        if (m >= M) break;
        float4 o;
        o.x = acc[i][0] + bi.x;
        o.y = acc[i][1] + bi.y;
        o.z = acc[i][2] + bi.z;
        o.w = acc[i][3] + bi.w;
        *(float4*)&C[(size_t)m*N + n0 + tx*4] = o;
    }
}

// ---------------- generic GEMM: C[M,N] = A[M,K] @ W[N,K]^T + bias ----------------
__global__ __launch_bounds__(256) void gemm_bias_k(
    const float* __restrict__ A, const float* __restrict__ W,
    const float* __restrict__ bias, float* __restrict__ C,
    int M, int N, int K)
{
    const int BM = 128, BN = 64, BK = 16;
    __shared__ __align__(16) float As[BK][BM+4];
    __shared__ __align__(16) float Bs[BK][BN+4];
    int tid = threadIdx.x;
    int tx = tid & 15;
    int ty = tid >> 4;
    int m0 = blockIdx.y * BM;
    int n0 = blockIdx.x * BN;

    float acc[8][4];
    #pragma unroll
    for (int i = 0; i < 8; i++)
        #pragma unroll
        for (int j = 0; j < 4; j++) acc[i][j] = 0.f;

    for (int k0 = 0; k0 < K; k0 += BK) {
        #pragma unroll
        for (int u = 0; u < 8; u++) {
            int idx = tid + u*256;
            int m = idx >> 4;
            int kk = idx & 15;
            int gm = m0 + m;
            As[kk][m] = (gm < M) ? A[(size_t)gm*K + k0 + kk] : 0.f;
        }
        #pragma unroll
        for (int u = 0; u < 4; u++) {
            int idx = tid + u*256;
            int n = idx >> 4;
            int kk = idx & 15;
            int gn = n0 + n;
            Bs[kk][n] = (gn < N) ? W[(size_t)gn*K + k0 + kk] : 0.f;
        }
        __syncthreads();
        #pragma unroll
        for (int kk = 0; kk < BK; kk++) {
            float4 a0 = *(const float4*)&As[kk][ty*8];
            float4 a1 = *(const float4*)&As[kk][ty*8 + 4];
            float4 b0 = *(const float4*)&Bs[kk][tx*4];
            float a[8] = {a0.x,a0.y,a0.z,a0.w,a1.x,a1.y,a1.z,a1.w};
            float bb[4] = {b0.x,b0.y,b0.z,b0.w};
            #pragma unroll
            for (int i = 0; i < 8; i++)
                #pragma unroll
                for (int j = 0; j < 4; j++)
                    acc[i][j] += a[i]*bb[j];
        }
        __syncthreads();
    }
    float4 bi = *(const float4*)&bias[n0 + tx*4];
    #pragma unroll
    for (int i = 0; i < 8; i++) {
        int m = m0 + ty*8 + i;
        if (m >= M) break;
        float4 o;
        o.x = acc[i][0] + bi.x;
        o.y = acc[i][1] + bi.y;
        o.z = acc[i][2] + bi.z;
        o.w = acc[i][3] + bi.w;
        *(float4*)&C[(size_t)m*N + n0 + tx*4] = o;
    }
}

// ---------------- (add +) LayerNorm over 512 cols ----------------
__global__ void add_ln_k(const float* __restrict__ X, const float* __restrict__ Y,
                         const float* __restrict__ g, const float* __restrict__ b,
                         float* __restrict__ out)
{
    int row = blockIdx.x;
    int t = threadIdx.x;          // 128 threads, 4 cols each
    float4 v = ((const float4*)(X + (size_t)row*E_))[t];
    if (Y) {
        float4 w = ((const float4*)(Y + (size_t)row*E_))[t];
        v.x += w.x; v.y += w.y; v.z += w.z; v.w += w.w;
    }
    float s  = v.x + v.y + v.z + v.w;
    float s2 = v.x*v.x + v.y*v.y + v.z*v.z + v.w*v.w;
    __shared__ float red[8];
    #pragma unroll
    for (int o = 16; o; o >>= 1) {
        s  += __shfl_xor_sync(0xffffffffu, s,  o);
        s2 += __shfl_xor_sync(0xffffffffu, s2, o);
    }
    int warp = t >> 5, lane = t & 31;
    if (lane == 0) { red[warp] = s; red[4+warp] = s2; }
    __syncthreads();
    s  = red[0] + red[1] + red[2] + red[3];
    s2 = red[4] + red[5] + red[6] + red[7];
    float mu  = s  * (1.f/E_);
    float var = s2 * (1.f/E_) - mu*mu;
    float inv = rsqrtf(var + 1e-5f);
    float4 gg = ((const float4*)g)[t];
    float4 bb = ((const float4*)b)[t];
    float4 o;
    o.x = (v.x - mu)*inv*gg.x + bb.x;
    o.y = (v.y - mu)*inv*gg.y + bb.y;
    o.z = (v.z - mu)*inv*gg.z + bb.z;
    o.w = (v.w - mu)*inv*gg.w + bb.w;
    ((float4*)(out + (size_t)row*E_))[t] = o;
}

// ---------------- attention: one block per (b, h) ----------------
__global__ __launch_bounds__(256) void attention_k()
{
    int b = blockIdx.x >> 3;
    int h = blockIdx.x & 7;
    __shared__ float q_sh[16][64];
    __shared__ float t_sh[32][65];
    __shared__ float sc[16][228];
    int tid = threadIdx.x;

    for (int i = tid; i < 16*64; i += 256) {
        int p = i >> 6, d = i & 63;
        q_sh[p][d] = g_q[(size_t)(b*16 + p)*E_ + h*64 + d];
    }
    __syncthreads();

    // scores
    for (int lc = 0; lc < L_; lc += 32) {
        int cnt = min(32, L_ - lc);
        for (int i = tid; i < cnt*64; i += 256) {
            int li = i >> 6, d = i & 63;
            t_sh[li][d] = g_kv[(size_t)(b*L_ + lc + li)*(2*E_) + h*64 + d];
        }
        __syncthreads();
        for (int t2 = tid; t2 < 16*32; t2 += 256) {
            int p = t2 >> 5, li = t2 & 31;
            if (lc + li < L_) {
                float s = 0.f;
                #pragma unroll
                for (int d = 0; d < 64; d++) s += q_sh[p][d] * t_sh[li][d];
                sc[p][lc + li] = s * 0.125f;
            }
        }
        __syncthreads();
    }

    // softmax (8 warps x 2 rows)
    int warp = tid >> 5, lane = tid & 31;
    for (int p = warp; p < 16; p += 8) {
        float mx = -1e30f;
        for (int l = lane; l < L_; l += 32) mx = fmaxf(mx, sc[p][l]);
        #pragma unroll
        for (int o = 16; o; o >>= 1) mx = fmaxf(mx, __shfl_xor_sync(0xffffffffu, mx, o));
        float sm = 0.f;
        for (int l = lane; l < L_; l += 32) {
            float e = expf(sc[p][l] - mx);
            sc[p][l] = e;
            sm += e;
        }
        #pragma unroll
        for (int o = 16; o; o >>= 1) sm += __shfl_xor_sync(0xffffffffu, sm, o);
        float invs = 1.f / sm;
        for (int l = lane; l < L_; l += 32) sc[p][l] *= invs;
    }
    __syncthreads();

    // out = attn @ V
    float acc[4] = {0.f, 0.f, 0.f, 0.f};
    for (int lc = 0; lc < L_; lc += 32) {
        int cnt = min(32, L_ - lc);
        for (int i = tid; i < cnt*64; i += 256) {
            int li = i >> 6, d = i & 63;
            t_sh[li][d] = g_kv[(size_t)(b*L_ + lc + li)*(2*E_) + E_ + h*64 + d];
        }
        __syncthreads();
        #pragma unroll
        for (int u = 0; u < 4; u++) {
            int idx = tid + u*256;
            int p = idx >> 6, d = idx & 63;
            for (int li = 0; li < cnt; li++)
                acc[u] += sc[p][lc + li] * t_sh[li][d];
        }
        __syncthreads();
    }
    #pragma unroll
    for (int u = 0; u < 4; u++) {
        int idx = tid + u*256;
        int p = idx >> 6, d = idx & 63;
        g_attn[(size_t)(b*16 + p)*E_ + h*64 + d] = acc[u];
    }
}

// ---------------- GELU(exact) + residual ----------------
__global__ void gelu_add_k()
{
    int idx = blockIdx.x*256 + threadIdx.x;     // 65536
    if (idx >= PROWS_*E_) return;
    float x = g_x[idx];
    float gl = 0.5f * x * (1.f + erff(x * 0.70710678118654752f));
    g_x[idx] = gl + g_res[idx];
}

// ---------------- outs = x @ Wc^T + bc ----------------
__global__ void outs_k(const float* __restrict__ Wc, const float* __restrict__ bc)
{
    int t = threadIdx.x;            // 256: (row, j)
    int row = t >> 1, j = t & 1;
    const float* xr = g_x + (size_t)row*E_;
    const float* wr = Wc + (size_t)j*E_;
    float s = 0.f;
    for (int k = 0; k < E_; k++) s += xr[k]*wr[k];
    g_outs[row*2 + j] = s + bc[j];
}

// ---------------- segment stats ----------------
__global__ void zero_stats_k()
{
    int t = threadIdx.x;
    if (t < B_*17*3) g_sums[t] = 0.f;
    if (t < B_*17)   g_cnt[t]  = 0.f;
}

__global__ void segsum_k(const float* __restrict__ probs, const int* __restrict__ masks)
{
    int b = blockIdx.x >> 4;
    int chunk = blockIdx.x & 15;
    __shared__ float s_sum[17*3];
    __shared__ float s_cnt[17];
    int t = threadIdx.x;            // 256
    if (t < 51) s_sum[t] = 0.f;
    if (t < 17) s_cnt[t] = 0.f;
    __syncthreads();
    const int* mrow = masks + (size_t)b*65536;
    const float* p0 = probs + (size_t)b*3*65536;
    int base = chunk*4096;
    for (int u = 0; u < 16; u++) {
        int pix = base + u*256 + t;
        int lab = mrow[pix];
        atomicAdd(&s_cnt[lab], 1.f);
        atomicAdd(&s_sum[lab*3 + 0], p0[pix]);
        atomicAdd(&s_sum[lab*3 + 1], p0[65536 + pix]);
        atomicAdd(&s_sum[lab*3 + 2], p0[131072 + pix]);
    }
    __syncthreads();
    if (t < 51) atomicAdd(&g_sums[b*51 + t], s_sum[t]);
    if (t < 17) atomicAdd(&g_cnt[b*17 + t],  s_cnt[t]);
}

__global__ void newv_k()
{
    int t = threadIdx.x;            // 128
    if (t >= 128) return;
    int b = t >> 4, p = t & 15;
    int lab = p + 1;
    float c = fmaxf(g_cnt[b*17 + lab], 1.f);
    float m0 = g_sums[b*51 + lab*3 + 0]/c + 1e-6f;
    float m1 = g_sums[b*51 + lab*3 + 1]/c + 1e-6f;
    float m2 = g_sums[b*51 + lab*3 + 2]/c + 1e-6f;
    int row = b*16 + p;
    float o0 = g_outs[row*2 + 0];
    float o1 = g_outs[row*2 + 1];
    float om = 0.5f*(o0 + o1);
    float new0 = m0 / (0.5f*(m1 + m2)) * om;
    g_newv[(b*17 + lab)*3 + 0] = new0;
    g_newv[(b*17 + lab)*3 + 1] = o0;
    g_newv[(b*17 + lab)*3 + 2] = o1;
    if (p == 0) {
        g_newv[(b*17)*3 + 0] = 0.f;
        g_newv[(b*17)*3 + 1] = 0.f;
        g_newv[(b*17)*3 + 2] = 0.f;
    }
}

// ---------------- final scatter ----------------
__global__ void scatter_k(const float* __restrict__ probs, const int* __restrict__ masks,
                          float* __restrict__ out)
{
    int idx = blockIdx.x*256 + threadIdx.x;     // 524288 pixels
    if (idx >= B_*65536) return;
    int b = idx >> 16;
    int pix = idx & 65535;
    int lab = masks[idx];
    float* o = out + (size_t)b*3*65536 + pix;
    if (lab > 0) {
        const float* v = &g_newv[(b*17 + lab)*3];
        o[0]      = v[0];
        o[65536]  = v[1];
        o[131072] = v[2];
    } else {
        const float* p = probs + (size_t)b*3*65536 + pix;
        o[0]      = p[0];
        o[65536]  = p[65536];
        o[131072] = p[131072];
    }
}

// ---------------- launch ----------------
static float* sym_addr(const void* symbol)
{
    void* p = nullptr;
    cudaGetSymbolAddress(&p, symbol);
    return (float*)p;
}

extern "C" void kernel_launch(void* const* d_in, const int* in_sizes, int n_in,
                              void* d_out, int out_size)
{
    const float* features = (const float*)d_in[0];
    const float* probs    = (const float*)d_in[1];
    const float* patches  = (const float*)d_in[2];
    const int*   masks    = (const int*)  d_in[3];
    const float* ln_g     = (const float*)d_in[4];
    const float* ln_b     = (const float*)d_in[5];
    const float* Wr       = (const float*)d_in[6];
    const float* br       = (const float*)d_in[7];
    const float* Wqkv     = (const float*)d_in[8];
    const float* bqkv     = (const float*)d_in[9];
    const float* Wo       = (const float*)d_in[10];
    const float* bo       = (const float*)d_in[11];
    const float* Wm       = (const float*)d_in[12];
    const float* bm       = (const float*)d_in[13];
    const float* Wc       = (const float*)d_in[14];
    const float* bc       = (const float*)d_in[15];
    float* out = (float*)d_out;

    float* emb   = sym_addr(g_emb);
    float* q     = sym_addr(g_q);
    float* kv    = sym_addr(g_kv);
    float* attn  = sym_addr(g_attn);
    float* attnp = sym_addr(g_attnp);
    float* res   = sym_addr(g_res);
    float* x     = sym_addr(g_x);

    // 1. pooling
    pool_features_k<<<(B_*16*128*128 + 255)/256, 256>>>(features);
    pool_patches_k<<<(PROWS_*FV_ + 255)/256, 256>>>(patches);

    // 2. embedding GEMM (fused block gather): [1928, 4096] x [512, 4096]^T
    gemm_emb_k<<<dim3(E_/64, (ROWS_ + 127)/128), 256>>>(Wr, br, emb);

    // 3. LayerNorm (in place)
    add_ln_k<<<ROWS_, 128>>>(emb, nullptr, ln_g, ln_b, emb);

    // 4. projections
    gemm_bias_k<<<dim3(E_/64, 1), 256>>>(emb, Wqkv, bqkv, q, PROWS_, E_, E_);
    gemm_bias_k<<<dim3(2*E_/64, (BROWS_ + 127)/128), 256>>>(emb + (size_t)PROWS_*E_,
                                                            Wqkv + (size_t)E_*E_, bqkv + E_,
                                                            kv, BROWS_, 2*E_, E_);

    // 5. attention
    attention_k<<<B_*HEADS_, 256>>>();

    // 6. output proj + residual LN
    gemm_bias_k<<<dim3(E_/64, 1), 256>>>(attn, Wo, bo, attnp, PROWS_, E_, E_);
    add_ln_k<<<PROWS_, 128>>>(attnp, emb, ln_g, ln_b, res);

    // 7. MLP
    gemm_bias_k<<<dim3(E_/64, 1), 256>>>(res, Wm, bm, x, PROWS_, E_, E_);
    gelu_add_k<<<(PROWS_*E_ + 255)/256, 256>>>();
    outs_k<<<1, 256>>>(Wc, bc);

    // 8. segment stats
    zero_stats_k<<<1, 512>>>();
    segsum_k<<<B_*16, 256>>>(probs, masks);
    newv_k<<<1, 128>>>();

    // 9. scatter
    scatter_k<<<(B_*65536 + 255)/256, 256>>>(probs, masks, out);
}

// round 3
// speedup vs baseline: 1.4200x; 1.4200x over previous
#include <cuda_runtime.h>
#include <math.h>
#include <stdint.h>

#define B_     8
#define C_     64
#define E_     512
#define HEADS_ 8
#define PD_    32
#define P_     16
#define NB_    15           // n = (256-32)/16+1
#define L_     225          // n*n
#define FV_    4096         // (C/4)*16*16
#define PROWS_ 128          // B*P
#define BROWS_ 1800         // B*L
#define ROWS_  1928         // PROWS_+BROWS_

// ---------------- scratch (device globals; no allocation) ----------------
__device__ float g_pooledF[B_*16*128*128];     // pooled features [b][cg][128][128]
__device__ float g_Apatch[(size_t)PROWS_*FV_]; // pooled patch vectors (rows 0..127)
__device__ float g_emb[ROWS_*E_];              // embeddings (post LN, in place)
__device__ float g_q[PROWS_*E_];
__device__ float g_kv[BROWS_*2*E_];            // per row: [k(512) | v(512)]
__device__ float g_attn[PROWS_*E_];
__device__ float g_attnp[PROWS_*E_];
__device__ float g_res[PROWS_*E_];
__device__ float g_x[PROWS_*E_];
__device__ float g_outs[PROWS_*2];
__device__ float g_sums[B_*17*3];
__device__ float g_cnt[B_*17];
__device__ float g_newv[B_*17*3];

// ---------------- pooling ----------------
__global__ void pool_features_k(const float* __restrict__ features)
{
    int idx = blockIdx.x*256 + threadIdx.x;           // 2,097,152 total
    if (idx >= B_*16*128*128) return;
    int x  = idx & 127;
    int y  = (idx >> 7) & 127;
    int cg = (idx >> 14) & 15;
    int b  = idx >> 18;
    const float* f = features + (((size_t)(b*64 + cg*4))*256 + 2*y)*256 + 2*x;
    float s = 0.f;
    #pragma unroll
    for (int c4 = 0; c4 < 4; c4++) {
        const float* fc = f + (size_t)c4*65536;
        s += fc[0] + fc[1] + fc[256] + fc[257];
    }
    g_pooledF[idx] = s * 0.0625f;
}

__global__ void pool_patches_k(const float* __restrict__ patches)
{
    int idx = blockIdx.x*256 + threadIdx.x;           // 128*4096 = 524288
    if (idx >= PROWS_*FV_) return;
    int k   = idx & 4095;
    int row = idx >> 12;
    int xx = k & 15;
    int yy = (k >> 4) & 15;
    int cg = k >> 8;
    const float* f = patches + (((size_t)row*64 + cg*4)*32 + 2*yy)*32 + 2*xx;
    float s = 0.f;
    #pragma unroll
    for (int c4 = 0; c4 < 4; c4++) {
        const float* fc = f + c4*1024;
        s += fc[0] + fc[1] + fc[32] + fc[33];
    }
    g_Apatch[(size_t)row*FV_ + k] = s * 0.0625f;
}

// ---------------- TF32 helpers ----------------
__device__ __forceinline__ void tf32split(float x, uint32_t &h, uint32_t &l)
{
    uint32_t hb;
    asm("cvt.rna.tf32.f32 %0, %1;" : "=r"(hb) : "f"(x));
    float hf = __uint_as_float(hb);
    float lf = x - hf;
    uint32_t lb;
    asm("cvt.rna.tf32.f32 %0, %1;" : "=r"(lb) : "f"(lf));
    h = hb; l = lb;
}

__device__ __forceinline__ void mma8(float* d,
    uint32_t a0, uint32_t a1, uint32_t a2, uint32_t a3,
    uint32_t b0, uint32_t b1)
{
    asm volatile("mma.sync.aligned.m16n8k8.row.col.f32.tf32.tf32.f32 "
        "{%0,%1,%2,%3}, {%4,%5,%6,%7}, {%8,%9}, {%0,%1,%2,%3};"
        : "+f"(d[0]), "+f"(d[1]), "+f"(d[2]), "+f"(d[3])
        : "r"(a0), "r"(a1), "r"(a2), "r"(a3), "r"(b0), "r"(b1));
}

// ---------------- tensor-core GEMM: C[M,N] = A[M,K] @ W[N,K]^T + bias -----
// BM=128, BN=64, BK=16, 256 threads, warps 4(m) x 2(n), warp tile 32x32.
// 3xTF32 split (hi/lo computed in registers from fp32 smem tiles).
// emb_mode==1: A is virtual (rows 0..127 from g_Apatch, rest gathered from g_pooledF).
__global__ __launch_bounds__(256) void gemm_tc_k(
    const float* __restrict__ A, const float* __restrict__ W,
    const float* __restrict__ bias, float* __restrict__ C,
    int M, int N, int K, int emb_mode)
{
    __shared__ float sA[128*16];
    __shared__ float sB[64*16];

    int tid  = threadIdx.x;
    int lane = tid & 31;
    int warp = tid >> 5;
    int g4   = lane >> 2;
    int lc   = lane & 3;
    int wm   = (warp >> 1) * 32;
    int wn   = (warp & 1) * 32;
    int m0   = blockIdx.y * 128;
    int n0   = blockIdx.x * 64;

    // ---- A loader setup (2 float4 per thread per iter) ----
    const float* apt[2];
    int amode[2], am[2], aj[2];
    #pragma unroll
    for (int u = 0; u < 2; u++) {
        int t = tid + u*256;
        int m = t >> 2;
        int j = t & 3;
        am[u] = m; aj[u] = j;
        int gm = m0 + m;
        if (!emb_mode) {
            if (gm < M) { apt[u] = A + (size_t)gm*K + j*4; amode[u] = 0; }
            else        { apt[u] = A; amode[u] = 2; }
        } else {
            if (gm < PROWS_) {
                apt[u] = g_Apatch + (size_t)gm*FV_ + j*4; amode[u] = 0;
            } else if (gm < ROWS_) {
                int r2 = gm - PROWS_;
                int b = r2 / L_;
                int l = r2 - b*L_;
                int r = l / NB_;
                int c = l - r*NB_;
                apt[u] = g_pooledF + (size_t)b*16*16384 + r*8*128 + c*8 + j*4;
                amode[u] = 1;
            } else { apt[u] = g_Apatch; amode[u] = 2; }
        }
    }
    // ---- B loader setup (1 float4 per thread) ----
    int bn = tid >> 2;
    int bj = tid & 3;
    const float* bpt = W + (size_t)(n0 + bn)*K + bj*4;

    float acc[2][4][4];
    #pragma unroll
    for (int f = 0; f < 2; f++)
        #pragma unroll
        for (int g = 0; g < 4; g++)
            #pragma unroll
            for (int i = 0; i < 4; i++) acc[f][g][i] = 0.f;

    for (int k0 = 0; k0 < K; k0 += 16) {
        // load A tile (permuted: slot(m,c',j), c' = c ^ ((m>>1)&3), element k=j*4+c)
        #pragma unroll
        for (int u = 0; u < 2; u++) {
            float4 v = make_float4(0.f, 0.f, 0.f, 0.f);
            if (amode[u] == 0)      v = *(const float4*)(apt[u] + k0);
            else if (amode[u] == 1) v = *(const float4*)(apt[u] + ((k0 >> 8) << 14) + (((k0 >> 4) & 15) << 7));
            int m = am[u], j = aj[u];
            int base = m*16 + j;
            int sw = (m >> 1) & 3;
            sA[base + ((0 ^ sw) << 2)] = v.x;
            sA[base + ((1 ^ sw) << 2)] = v.y;
            sA[base + ((2 ^ sw) << 2)] = v.z;
            sA[base + ((3 ^ sw) << 2)] = v.w;
        }
        {
            float4 v = *(const float4*)(bpt + k0);
            int base = bn*16 + bj;
            int sw = (bn >> 1) & 3;
            sB[base + ((0 ^ sw) << 2)] = v.x;
            sB[base + ((1 ^ sw) << 2)] = v.y;
            sB[base + ((2 ^ sw) << 2)] = v.z;
            sB[base + ((3 ^ sw) << 2)] = v.w;
        }
        __syncthreads();

        // B fragments: 4 n-frags; float4 holds k = lc, lc+4, lc+8, lc+12
        uint32_t bh[4][4], bl[4][4];
        #pragma unroll
        for (int g = 0; g < 4; g++) {
            int nn = wn + g*8 + g4;
            int cp = lc ^ ((nn >> 1) & 3);
            float4 bv = *(float4*)&sB[nn*16 + cp*4];
            tf32split(bv.x, bh[g][0], bl[g][0]);
            tf32split(bv.y, bh[g][1], bl[g][1]);
            tf32split(bv.z, bh[g][2], bl[g][2]);
            tf32split(bv.w, bh[g][3], bl[g][3]);
        }

        #pragma unroll
        for (int f = 0; f < 2; f++) {
            int mr0 = wm + f*16 + g4;
            int mr1 = mr0 + 8;
            int cp0 = lc ^ ((mr0 >> 1) & 3);
            int cp1 = lc ^ ((mr1 >> 1) & 3);
            float4 a0v = *(float4*)&sA[mr0*16 + cp0*4];
            float4 a1v = *(float4*)&sA[mr1*16 + cp1*4];
            uint32_t ah[2][4], al[2][4];
            tf32split(a0v.x, ah[0][0], al[0][0]);
            tf32split(a0v.y, ah[0][1], al[0][1]);
            tf32split(a0v.z, ah[0][2], al[0][2]);
            tf32split(a0v.w, ah[0][3], al[0][3]);
            tf32split(a1v.x, ah[1][0], al[1][0]);
            tf32split(a1v.y, ah[1][1], al[1][1]);
            tf32split(a1v.z, ah[1][2], al[1][2]);
            tf32split(a1v.w, ah[1][3], al[1][3]);

            #pragma unroll
            for (int g = 0; g < 4; g++) {
                float* d = acc[f][g];
                // k-step 0 (k = 0..7 of this chunk)
                mma8(d, ah[0][0], ah[1][0], ah[0][1], ah[1][1], bh[g][0], bh[g][1]); // hi*hi
                mma8(d, ah[0][0], ah[1][0], ah[0][1], ah[1][1], bl[g][0], bl[g][1]); // hi*lo
                mma8(d, al[0][0], al[1][0], al[0][1], al[1][1], bh[g][0], bh[g][1]); // lo*hi
                // k-step 1 (k = 8..15)
                mma8(d, ah[0][2], ah[1][2], ah[0][3], ah[1][3], bh[g][2], bh[g][3]);
                mma8(d, ah[0][2], ah[1][2], ah[0][3], ah[1][3], bl[g][2], bl[g][3]);
                mma8(d, al[0][2], al[1][2], al[0][3], al[1][3], bh[g][2], bh[g][3]);
            }
        }
        __syncthreads();
    }

    // ---- epilogue ----
    #pragma unroll
    for (int f = 0; f < 2; f++) {
        int row0 = m0 + wm + f*16 + g4;
        #pragma unroll
        for (int g = 0; g < 4; g++) {
            int col = n0 + wn + g*8 + lc*2;
            float b0 = bias[col], b1 = bias[col + 1];
            if (row0 < M) {
                float2 o; o.x = acc[f][g][0] + b0; o.y = acc[f][g][1] + b1;
                *(float2*)&C[(size_t)row0*N + col] = o;
            }
            int row1 = row0 + 8;
            if (row1 < M) {
                float2 o; o.x = acc[f][g][2] + b0; o.y = acc[f][g][3] + b1;
                *(float2*)&C[(size_t)row1*N + col] = o;
            }
        }
    }
}

// ---------------- (add +) LayerNorm over 512 cols ----------------
__global__ void add_ln_k(const float* __restrict__ X, const float* __restrict__ Y,
                         const float* __restrict__ g, const float* __restrict__ b,
                         float* __restrict__ out)
{
    int row = blockIdx.x;
    int t = threadIdx.x;          // 128 threads, 4 cols each
    float4 v = ((const float4*)(X + (size_t)row*E_))[t];
    if (Y) {
        float4 w = ((const float4*)(Y + (size_t)row*E_))[t];
        v.x += w.x; v.y += w.y; v.z += w.z; v.w += w.w;
    }
    float s  = v.x + v.y + v.z + v.w;
    float s2 = v.x*v.x + v.y*v.y + v.z*v.z + v.w*v.w;
    __shared__ float red[8];
    #pragma unroll
    for (int o = 16; o; o >>= 1) {
        s  += __shfl_xor_sync(0xffffffffu, s,  o);
        s2 += __shfl_xor_sync(0xffffffffu, s2, o);
    }
    int warp = t >> 5, lane = t & 31;
    if (lane == 0) { red[warp] = s; red[4+warp] = s2; }
    __syncthreads();
    s  = red[0] + red[1] + red[2] + red[3];
    s2 = red[4] + red[5] + red[6] + red[7];
    float mu  = s  * (1.f/E_);
    float var = s2 * (1.f/E_) - mu*mu;
    float inv = rsqrtf(var + 1e-5f);
    float4 gg = ((const float4*)g)[t];
    float4 bb = ((const float4*)b)[t];
    float4 o;
    o.x = (v.x - mu)*inv*gg.x + bb.x;
    o.y = (v.y - mu)*inv*gg.y + bb.y;
    o.z = (v.z - mu)*inv*gg.z + bb.z;
    o.w = (v.w - mu)*inv*gg.w + bb.w;
    ((float4*)(out + (size_t)row*E_))[t] = o;
}

// ---------------- attention: one block per (b, h) ----------------
__global__ __launch_bounds__(256) void attention_k()
{
    int b = blockIdx.x >> 3;
    int h = blockIdx.x & 7;
    __shared__ float q_sh[16][64];
    __shared__ float t_sh[32][65];
    __shared__ float sc[16][228];
    int tid = threadIdx.x;

    for (int i = tid; i < 16*64; i += 256) {
        int p = i >> 6, d = i & 63;
        q_sh[p][d] = g_q[(size_t)(b*16 + p)*E_ + h*64 + d];
    }
    __syncthreads();

    for (int lc = 0; lc < L_; lc += 32) {
        int cnt = min(32, L_ - lc);
        for (int i = tid; i < cnt*64; i += 256) {
            int li = i >> 6, d = i & 63;
            t_sh[li][d] = g_kv[(size_t)(b*L_ + lc + li)*(2*E_) + h*64 + d];
        }
        __syncthreads();
        for (int t2 = tid; t2 < 16*32; t2 += 256) {
            int p = t2 >> 5, li = t2 & 31;
            if (lc + li < L_) {
                float s = 0.f;
                #pragma unroll
                for (int d = 0; d < 64; d++) s += q_sh[p][d] * t_sh[li][d];
                sc[p][lc + li] = s * 0.125f;
            }
        }
        __syncthreads();
    }

    int warp = tid >> 5, lane = tid & 31;
    for (int p = warp; p < 16; p += 8) {
        float mx = -1e30f;
        for (int l = lane; l < L_; l += 32) mx = fmaxf(mx, sc[p][l]);
        #pragma unroll
        for (int o = 16; o; o >>= 1) mx = fmaxf(mx, __shfl_xor_sync(0xffffffffu, mx, o));
        float sm = 0.f;
        for (int l = lane; l < L_; l += 32) {
            float e = expf(sc[p][l] - mx);
            sc[p][l] = e;
            sm += e;
        }
        #pragma unroll
        for (int o = 16; o; o >>= 1) sm += __shfl_xor_sync(0xffffffffu, sm, o);
        float invs = 1.f / sm;
        for (int l = lane; l < L_; l += 32) sc[p][l] *= invs;
    }
    __syncthreads();

    float acc[4] = {0.f, 0.f, 0.f, 0.f};
    for (int lc = 0; lc < L_; lc += 32) {
        int cnt = min(32, L_ - lc);
        for (int i = tid; i < cnt*64; i += 256) {
            int li = i >> 6, d = i & 63;
            t_sh[li][d] = g_kv[(size_t)(b*L_ + lc + li)*(2*E_) + E_ + h*64 + d];
        }
        __syncthreads();
        #pragma unroll
        for (int u = 0; u < 4; u++) {
            int idx = tid + u*256;
            int p = idx >> 6, d = idx & 63;
            for (int li = 0; li < cnt; li++)
                acc[u] += sc[p][lc + li] * t_sh[li][d];
        }
        __syncthreads();
    }
    #pragma unroll
    for (int u = 0; u < 4; u++) {
        int idx = tid + u*256;
        int p = idx >> 6, d = idx & 63;
        g_attn[(size_t)(b*16 + p)*E_ + h*64 + d] = acc[u];
    }
}

// ---------------- GELU(exact) + residual ----------------
__global__ void gelu_add_k()
{
    int idx = blockIdx.x*256 + threadIdx.x;     // 65536
    if (idx >= PROWS_*E_) return;
    float x = g_x[idx];
    float gl = 0.5f * x * (1.f + erff(x * 0.70710678118654752f));
    g_x[idx] = gl + g_res[idx];
}

// ---------------- outs = x @ Wc^T + bc ----------------
__global__ void outs_k(const float* __restrict__ Wc, const float* __restrict__ bc)
{
    int t = threadIdx.x;            // 256: (row, j)
    int row = t >> 1, j = t & 1;
    const float* xr = g_x + (size_t)row*E_;
    const float* wr = Wc + (size_t)j*E_;
    float s = 0.f;
    for (int k = 0; k < E_; k++) s += xr[k]*wr[k];
    g_outs[row*2 + j] = s + bc[j];
}

// ---------------- segment stats ----------------
__global__ void zero_stats_k()
{
    int t = threadIdx.x;
    if (t < B_*17*3) g_sums[t] = 0.f;
    if (t < B_*17)   g_cnt[t]  = 0.f;
}

__global__ void segsum_k(const float* __restrict__ probs, const int* __restrict__ masks)
{
    int b = blockIdx.x >> 4;
    int chunk = blockIdx.x & 15;
    __shared__ float s_sum[17*3];
    __shared__ float s_cnt[17];
    int t = threadIdx.x;            // 256
    if (t < 51) s_sum[t] = 0.f;
    if (t < 17) s_cnt[t] = 0.f;
    __syncthreads();
    const int* mrow = masks + (size_t)b*65536;
    const float* p0 = probs + (size_t)b*3*65536;
    int base = chunk*4096;
    for (int u = 0; u < 16; u++) {
        int pix = base + u*256 + t;
        int lab = mrow[pix];
        atomicAdd(&s_cnt[lab], 1.f);
        atomicAdd(&s_sum[lab*3 + 0], p0[pix]);
        atomicAdd(&s_sum[lab*3 + 1], p0[65536 + pix]);
        atomicAdd(&s_sum[lab*3 + 2], p0[131072 + pix]);
    }
    __syncthreads();
    if (t < 51) atomicAdd(&g_sums[b*51 + t], s_sum[t]);
    if (t < 17) atomicAdd(&g_cnt[b*17 + t],  s_cnt[t]);
}

__global__ void newv_k()
{
    int t = threadIdx.x;            // 128
    if (t >= 128) return;
    int b = t >> 4, p = t & 15;
    int lab = p + 1;
    float c = fmaxf(g_cnt[b*17 + lab], 1.f);
    float m0 = g_sums[b*51 + lab*3 + 0]/c + 1e-6f;
    float m1 = g_sums[b*51 + lab*3 + 1]/c + 1e-6f;
    float m2 = g_sums[b*51 + lab*3 + 2]/c + 1e-6f;
    int row = b*16 + p;
    float o0 = g_outs[row*2 + 0];
    float o1 = g_outs[row*2 + 1];
    float om = 0.5f*(o0 + o1);
    float new0 = m0 / (0.5f*(m1 + m2)) * om;
    g_newv[(b*17 + lab)*3 + 0] = new0;
    g_newv[(b*17 + lab)*3 + 1] = o0;
    g_newv[(b*17 + lab)*3 + 2] = o1;
    if (p == 0) {
        g_newv[(b*17)*3 + 0] = 0.f;
        g_newv[(b*17)*3 + 1] = 0.f;
        g_newv[(b*17)*3 + 2] = 0.f;
    }
}

// ---------------- final scatter ----------------
__global__ void scatter_k(const float* __restrict__ probs, const int* __restrict__ masks,
                          float* __restrict__ out)
{
    int idx = blockIdx.x*256 + threadIdx.x;     // 524288 pixels
    if (idx >= B_*65536) return;
    int b = idx >> 16;
    int pix = idx & 65535;
    int lab = masks[idx];
    float* o = out + (size_t)b*3*65536 + pix;
    if (lab > 0) {
        const float* v = &g_newv[(b*17 + lab)*3];
        o[0]      = v[0];
        o[65536]  = v[1];
        o[131072] = v[2];
    } else {
        const float* p = probs + (size_t)b*3*65536 + pix;
        o[0]      = p[0];
        o[65536]  = p[65536];
        o[131072] = p[131072];
    }
}

// ---------------- launch ----------------
static float* sym_addr(const void* symbol)
{
    void* p = nullptr;
    cudaGetSymbolAddress(&p, symbol);
    return (float*)p;
}

extern "C" void kernel_launch(void* const* d_in, const int* in_sizes, int n_in,
                              void* d_out, int out_size)
{
    const float* features = (const float*)d_in[0];
    const float* probs    = (const float*)d_in[1];
    const float* patches  = (const float*)d_in[2];
    const int*   masks    = (const int*)  d_in[3];
    const float* ln_g     = (const float*)d_in[4];
    const float* ln_b     = (const float*)d_in[5];
    const float* Wr       = (const float*)d_in[6];
    const float* br       = (const float*)d_in[7];
    const float* Wqkv     = (const float*)d_in[8];
    const float* bqkv     = (const float*)d_in[9];
    const float* Wo       = (const float*)d_in[10];
    const float* bo       = (const float*)d_in[11];
    const float* Wm       = (const float*)d_in[12];
    const float* bm       = (const float*)d_in[13];
    const float* Wc       = (const float*)d_in[14];
    const float* bc       = (const float*)d_in[15];
    float* out = (float*)d_out;

    float* emb   = sym_addr(g_emb);
    float* q     = sym_addr(g_q);
    float* kv    = sym_addr(g_kv);
    float* attn  = sym_addr(g_attn);
    float* attnp = sym_addr(g_attnp);
    float* res   = sym_addr(g_res);
    float* x     = sym_addr(g_x);

    // 1. pooling
    pool_features_k<<<(B_*16*128*128 + 255)/256, 256>>>(features);
    pool_patches_k<<<(PROWS_*FV_ + 255)/256, 256>>>(patches);

    // 2. embedding GEMM (fused block gather): [1928, 4096] x [512, 4096]^T
    gemm_tc_k<<<dim3(E_/64, (ROWS_ + 127)/128), 256>>>(nullptr, Wr, br, emb,
                                                       ROWS_, E_, FV_, 1);

    // 3. LayerNorm (in place)
    add_ln_k<<<ROWS_, 128>>>(emb, nullptr, ln_g, ln_b, emb);

    // 4. projections
    gemm_tc_k<<<dim3(E_/64, 1), 256>>>(emb, Wqkv, bqkv, q, PROWS_, E_, E_, 0);
    gemm_tc_k<<<dim3(2*E_/64, (BROWS_ + 127)/128), 256>>>(emb + (size_t)PROWS_*E_,
                                                          Wqkv + (size_t)E_*E_, bqkv + E_,
                                                          kv, BROWS_, 2*E_, E_, 0);

    // 5. attention
    attention_k<<<B_*HEADS_, 256>>>();

    // 6. output proj + residual LN
    gemm_tc_k<<<dim3(E_/64, 1), 256>>>(attn, Wo, bo, attnp, PROWS_, E_, E_, 0);
    add_ln_k<<<PROWS_, 128>>>(attnp, emb, ln_g, ln_b, res);

    // 7. MLP
    gemm_tc_k<<<dim3(E_/64, 1), 256>>>(res, Wm, bm, x, PROWS_, E_, E_, 0);
    gelu_add_k<<<(PROWS_*E_ + 255)/256, 256>>>();
    outs_k<<<1, 256>>>(Wc, bc);

    // 8. segment stats
    zero_stats_k<<<1, 512>>>();
    segsum_k<<<B_*16, 256>>>(probs, masks);
    newv_k<<<1, 128>>>();

    // 9. scatter
    scatter_k<<<(B_*65536 + 255)/256, 256>>>(probs, masks, out);
}

// round 5
// speedup vs baseline: 2.3474x; 1.6531x over previous
#include <cuda_runtime.h>
#include <math.h>
#include <stdint.h>

#define B_     8
#define C_     64
#define E_     512
#define HEADS_ 8
#define PD_    32
#define P_     16
#define NB_    15           // n = (256-32)/16+1
#define L_     225          // n*n
#define FV_    4096         // (C/4)*16*16
#define PROWS_ 128          // B*P
#define BROWS_ 1800         // B*L
#define ROWS_  1928         // PROWS_+BROWS_

// ---------------- scratch (device globals; no allocation) ----------------
__device__ float g_pooledF[B_*16*128*128];     // pooled features [b][cg][128][128]
__device__ float g_Apatch[(size_t)PROWS_*FV_]; // pooled patch vectors (rows 0..127)
__device__ float g_emb[ROWS_*E_];              // embeddings (post LN, in place)
__device__ float g_q[PROWS_*E_];
__device__ float g_kv[BROWS_*2*E_];            // per row: [k(512) | v(512)]
__device__ float g_attn[PROWS_*E_];
__device__ float g_attnp[PROWS_*E_];
__device__ float g_res[PROWS_*E_];
__device__ float g_x[PROWS_*E_];
__device__ float g_outs[PROWS_*2];
__device__ float g_sums[B_*17*3];
__device__ float g_cnt[B_*17];
__device__ float g_newv[B_*17*3];

// ---------------- pooling ----------------
__global__ void pool_features_k(const float* __restrict__ features)
{
    int idx = blockIdx.x*256 + threadIdx.x;           // 2,097,152 total
    if (idx >= B_*16*128*128) return;
    int x  = idx & 127;
    int y  = (idx >> 7) & 127;
    int cg = (idx >> 14) & 15;
    int b  = idx >> 18;
    const float* f = features + (((size_t)(b*64 + cg*4))*256 + 2*y)*256 + 2*x;
    float s = 0.f;
    #pragma unroll
    for (int c4 = 0; c4 < 4; c4++) {
        const float* fc = f + (size_t)c4*65536;
        s += fc[0] + fc[1] + fc[256] + fc[257];
    }
    g_pooledF[idx] = s * 0.0625f;
}

__global__ void pool_patches_k(const float* __restrict__ patches)
{
    int idx = blockIdx.x*256 + threadIdx.x;           // 128*4096 = 524288
    if (idx >= PROWS_*FV_) return;
    int k   = idx & 4095;
    int row = idx >> 12;
    int xx = k & 15;
    int yy = (k >> 4) & 15;
    int cg = k >> 8;
    const float* f = patches + (((size_t)row*64 + cg*4)*32 + 2*yy)*32 + 2*xx;
    float s = 0.f;
    #pragma unroll
    for (int c4 = 0; c4 < 4; c4++) {
        const float* fc = f + c4*1024;
        s += fc[0] + fc[1] + fc[32] + fc[33];
    }
    g_Apatch[(size_t)row*FV_ + k] = s * 0.0625f;
}

// ---------------- TF32 helpers ----------------
__device__ __forceinline__ void tf32split(float x, uint32_t &h, uint32_t &l)
{
    uint32_t hb;
    asm("cvt.rna.tf32.f32 %0, %1;" : "=r"(hb) : "f"(x));
    float hf = __uint_as_float(hb);
    float lf = x - hf;
    uint32_t lb;
    asm("cvt.rna.tf32.f32 %0, %1;" : "=r"(lb) : "f"(lf));
    h = hb; l = lb;
}

__device__ __forceinline__ void mma8(float* d,
    uint32_t a0, uint32_t a1, uint32_t a2, uint32_t a3,
    uint32_t b0, uint32_t b1)
{
    asm volatile("mma.sync.aligned.m16n8k8.row.col.f32.tf32.tf32.f32 "
        "{%0,%1,%2,%3}, {%4,%5,%6,%7}, {%8,%9}, {%0,%1,%2,%3};"
        : "+f"(d[0]), "+f"(d[1]), "+f"(d[2]), "+f"(d[3])
        : "r"(a0), "r"(a1), "r"(a2), "r"(a3), "r"(b0), "r"(b1));
}

// ---------------- tensor-core GEMM: C[M,N] = A[M,K] @ W[N,K]^T + bias -----
// BM=128, BN=64, BK=16, 256 threads, warps 4(m) x 2(n), warp tile 32x32.
// 3xTF32 split; register double-buffering hides global-load latency.
// emb_mode==1: A is virtual (rows 0..127 from g_Apatch, rest gathered from g_pooledF).
__global__ __launch_bounds__(256) void gemm_tc_k(
    const float* __restrict__ A, const float* __restrict__ W,
    const float* __restrict__ bias, float* __restrict__ C,
    int M, int N, int K, int emb_mode)
{
    __shared__ float sA[128*16];
    __shared__ float sB[64*16];

    int tid  = threadIdx.x;
    int lane = tid & 31;
    int warp = tid >> 5;
    int g4   = lane >> 2;
    int lc   = lane & 3;
    int wm   = (warp >> 1) * 32;
    int wn   = (warp & 1) * 32;
    int m0   = blockIdx.y * 128;
    int n0   = blockIdx.x * 64;

    // ---- A loader setup (2 float4 per thread per iter) ----
    const float* apt[2];
    int amode[2], am[2], aj[2];
    #pragma unroll
    for (int u = 0; u < 2; u++) {
        int t = tid + u*256;
        int m = t >> 2;
        int j = t & 3;
        am[u] = m; aj[u] = j;
        int gm = m0 + m;
        if (!emb_mode) {
            if (gm < M) { apt[u] = A + (size_t)gm*K + j*4; amode[u] = 0; }
            else        { apt[u] = A; amode[u] = 2; }
        } else {
            if (gm < PROWS_) {
                apt[u] = g_Apatch + (size_t)gm*FV_ + j*4; amode[u] = 0;
            } else if (gm < ROWS_) {
                int r2 = gm - PROWS_;
                int b = r2 / L_;
                int l = r2 - b*L_;
                int r = l / NB_;
                int c = l - r*NB_;
                apt[u] = g_pooledF + (size_t)b*16*16384 + r*8*128 + c*8 + j*4;
                amode[u] = 1;
            } else { apt[u] = g_Apatch; amode[u] = 2; }
        }
    }
    // ---- B loader setup (1 float4 per thread) ----
    int bn = tid >> 2;
    int bj = tid & 3;
    const float* bpt = W + (size_t)(n0 + bn)*K + bj*4;

    float acc[2][4][4];
    #pragma unroll
    for (int f = 0; f < 2; f++)
        #pragma unroll
        for (int g = 0; g < 4; g++)
            #pragma unroll
            for (int i = 0; i < 4; i++) acc[f][g][i] = 0.f;

    // ---- prologue: load tile 0 into registers ----
    float4 ra[2], rb;
    #pragma unroll
    for (int u = 0; u < 2; u++) {
        ra[u] = make_float4(0.f, 0.f, 0.f, 0.f);
        if (amode[u] != 2) ra[u] = *(const float4*)(apt[u]);
    }
    rb = *(const float4*)(bpt);

    for (int k0 = 0; k0 < K; k0 += 16) {
        // ---- store current registers into swizzled smem ----
        #pragma unroll
        for (int u = 0; u < 2; u++) {
            int m = am[u], j = aj[u];
            int base = m*16 + j;
            int sw = (m >> 1) & 3;
            sA[base + ((0 ^ sw) << 2)] = ra[u].x;
            sA[base + ((1 ^ sw) << 2)] = ra[u].y;
            sA[base + ((2 ^ sw) << 2)] = ra[u].z;
            sA[base + ((3 ^ sw) << 2)] = ra[u].w;
        }
        {
            int base = bn*16 + bj;
            int sw = (bn >> 1) & 3;
            sB[base + ((0 ^ sw) << 2)] = rb.x;
            sB[base + ((1 ^ sw) << 2)] = rb.y;
            sB[base + ((2 ^ sw) << 2)] = rb.z;
            sB[base + ((3 ^ sw) << 2)] = rb.w;
        }
        __syncthreads();

        // ---- prefetch next tile (latency hidden behind MMA below) ----
        int k1 = k0 + 16;
        if (k1 < K) {
            #pragma unroll
            for (int u = 0; u < 2; u++) {
                if (amode[u] == 0)      ra[u] = *(const float4*)(apt[u] + k1);
                else if (amode[u] == 1) ra[u] = *(const float4*)(apt[u] + ((k1 >> 8) << 14) + (((k1 >> 4) & 15) << 7));
            }
            rb = *(const float4*)(bpt + k1);
        }

        // ---- B fragments: 4 n-frags; float4 holds k = c, c+4, c+8, c+12 ----
        uint32_t bh[4][4], bl[4][4];
        #pragma unroll
        for (int g = 0; g < 4; g++) {
            int nn = wn + g*8 + g4;
            int cp = lc ^ ((nn >> 1) & 3);
            float4 bv = *(float4*)&sB[nn*16 + cp*4];
            tf32split(bv.x, bh[g][0], bl[g][0]);
            tf32split(bv.y, bh[g][1], bl[g][1]);
            tf32split(bv.z, bh[g][2], bl[g][2]);
            tf32split(bv.w, bh[g][3], bl[g][3]);
        }

        #pragma unroll
        for (int f = 0; f < 2; f++) {
            int mr0 = wm + f*16 + g4;
            int mr1 = mr0 + 8;
            int cp0 = lc ^ ((mr0 >> 1) & 3);
            int cp1 = lc ^ ((mr1 >> 1) & 3);
            float4 a0v = *(float4*)&sA[mr0*16 + cp0*4];
            float4 a1v = *(float4*)&sA[mr1*16 + cp1*4];
            uint32_t ah[2][4], al[2][4];
            tf32split(a0v.x, ah[0][0], al[0][0]);
            tf32split(a0v.y, ah[0][1], al[0][1]);
            tf32split(a0v.z, ah[0][2], al[0][2]);
            tf32split(a0v.w, ah[0][3], al[0][3]);
            tf32split(a1v.x, ah[1][0], al[1][0]);
            tf32split(a1v.y, ah[1][1], al[1][1]);
            tf32split(a1v.z, ah[1][2], al[1][2]);
            tf32split(a1v.w, ah[1][3], al[1][3]);

            #pragma unroll
            for (int g = 0; g < 4; g++) {
                float* d = acc[f][g];
                // k-step 0 (k = 0..7 of this chunk)
                mma8(d, ah[0][0], ah[1][0], ah[0][1], ah[1][1], bh[g][0], bh[g][1]); // hi*hi
                mma8(d, ah[0][0], ah[1][0], ah[0][1], ah[1][1], bl[g][0], bl[g][1]); // hi*lo
                mma8(d, al[0][0], al[1][0], al[0][1], al[1][1], bh[g][0], bh[g][1]); // lo*hi
                // k-step 1 (k = 8..15)
                mma8(d, ah[0][2], ah[1][2], ah[0][3], ah[1][3], bh[g][2], bh[g][3]);
                mma8(d, ah[0][2], ah[1][2], ah[0][3], ah[1][3], bl[g][2], bl[g][3]);
                mma8(d, al[0][2], al[1][2], al[0][3], al[1][3], bh[g][2], bh[g][3]);
            }
        }
        __syncthreads();
    }

    // ---- epilogue ----
    #pragma unroll
    for (int f = 0; f < 2; f++) {
        int row0 = m0 + wm + f*16 + g4;
        #pragma unroll
        for (int g = 0; g < 4; g++) {
            int col = n0 + wn + g*8 + lc*2;
            float b0 = bias[col], b1 = bias[col + 1];
            if (row0 < M) {
                float2 o; o.x = acc[f][g][0] + b0; o.y = acc[f][g][1] + b1;
                *(float2*)&C[(size_t)row0*N + col] = o;
            }
            int row1 = row0 + 8;
            if (row1 < M) {
                float2 o; o.x = acc[f][g][2] + b0; o.y = acc[f][g][3] + b1;
                *(float2*)&C[(size_t)row1*N + col] = o;
            }
        }
    }
}

// ---------------- (add +) LayerNorm over 512 cols ----------------
__global__ void add_ln_k(const float* __restrict__ X, const float* __restrict__ Y,
                         const float* __restrict__ g, const float* __restrict__ b,
                         float* __restrict__ out)
{
    int row = blockIdx.x;
    int t = threadIdx.x;          // 128 threads, 4 cols each
    float4 v = ((const float4*)(X + (size_t)row*E_))[t];
    if (Y) {
        float4 w = ((const float4*)(Y + (size_t)row*E_))[t];
        v.x += w.x; v.y += w.y; v.z += w.z; v.w += w.w;
    }
    float s  = v.x + v.y + v.z + v.w;
    float s2 = v.x*v.x + v.y*v.y + v.z*v.z + v.w*v.w;
    __shared__ float red[8];
    #pragma unroll
    for (int o = 16; o; o >>= 1) {
        s  += __shfl_xor_sync(0xffffffffu, s,  o);
        s2 += __shfl_xor_sync(0xffffffffu, s2, o);
    }
    int warp = t >> 5, lane = t & 31;
    if (lane == 0) { red[warp] = s; red[4+warp] = s2; }
    __syncthreads();
    s  = red[0] + red[1] + red[2] + red[3];
    s2 = red[4] + red[5] + red[6] + red[7];
    float mu  = s  * (1.f/E_);
    float var = s2 * (1.f/E_) - mu*mu;
    float inv = rsqrtf(var + 1e-5f);
    float4 gg = ((const float4*)g)[t];
    float4 bb = ((const float4*)b)[t];
    float4 o;
    o.x = (v.x - mu)*inv*gg.x + bb.x;
    o.y = (v.y - mu)*inv*gg.y + bb.y;
    o.z = (v.z - mu)*inv*gg.z + bb.z;
    o.w = (v.w - mu)*inv*gg.w + bb.w;
    ((float4*)(out + (size_t)row*E_))[t] = o;
}

// ---------------- attention: one block per (b, h) ----------------
__global__ __launch_bounds__(256) void attention_k()
{
    int b = blockIdx.x >> 3;
    int h = blockIdx.x & 7;
    __shared__ float q_sh[16][64];
    __shared__ float t_sh[32][65];
    __shared__ float sc[16][228];
    int tid = threadIdx.x;

    for (int i = tid; i < 16*64; i += 256) {
        int p = i >> 6, d = i & 63;
        q_sh[p][d] = g_q[(size_t)(b*16 + p)*E_ + h*64 + d];
    }
    __syncthreads();

    for (int lc = 0; lc < L_; lc += 32) {
        int cnt = min(32, L_ - lc);
        for (int i = tid; i < cnt*64; i += 256) {
            int li = i >> 6, d = i & 63;
            t_sh[li][d] = g_kv[(size_t)(b*L_ + lc + li)*(2*E_) + h*64 + d];
        }
        __syncthreads();
        for (int t2 = tid; t2 < 16*32; t2 += 256) {
            int p = t2 >> 5, li = t2 & 31;
            if (lc + li < L_) {
                float s = 0.f;
                #pragma unroll
                for (int d = 0; d < 64; d++) s += q_sh[p][d] * t_sh[li][d];
                sc[p][lc + li] = s * 0.125f;
            }
        }
        __syncthreads();
    }

    int warp = tid >> 5, lane = tid & 31;
    for (int p = warp; p < 16; p += 8) {
        float mx = -1e30f;
        for (int l = lane; l < L_; l += 32) mx = fmaxf(mx, sc[p][l]);
        #pragma unroll
        for (int o = 16; o; o >>= 1) mx = fmaxf(mx, __shfl_xor_sync(0xffffffffu, mx, o));
        float sm = 0.f;
        for (int l = lane; l < L_; l += 32) {
            float e = expf(sc[p][l] - mx);
            sc[p][l] = e;
            sm += e;
        }
        #pragma unroll
        for (int o = 16; o; o >>= 1) sm += __shfl_xor_sync(0xffffffffu, sm, o);
        float invs = 1.f / sm;
        for (int l = lane; l < L_; l += 32) sc[p][l] *= invs;
    }
    __syncthreads();

    float acc[4] = {0.f, 0.f, 0.f, 0.f};
    for (int lc = 0; lc < L_; lc += 32) {
        int cnt = min(32, L_ - lc);
        for (int i = tid; i < cnt*64; i += 256) {
            int li = i >> 6, d = i & 63;
            t_sh[li][d] = g_kv[(size_t)(b*L_ + lc + li)*(2*E_) + E_ + h*64 + d];
        }
        __syncthreads();
        #pragma unroll
        for (int u = 0; u < 4; u++) {
            int idx = tid + u*256;
            int p = idx >> 6, d = idx & 63;
            for (int li = 0; li < cnt; li++)
                acc[u] += sc[p][lc + li] * t_sh[li][d];
        }
        __syncthreads();
    }
    #pragma unroll
    for (int u = 0; u < 4; u++) {
        int idx = tid + u*256;
        int p = idx >> 6, d = idx & 63;
        g_attn[(size_t)(b*16 + p)*E_ + h*64 + d] = acc[u];
    }
}

// ---------------- GELU(exact) + residual ----------------
__global__ void gelu_add_k()
{
    int idx = blockIdx.x*256 + threadIdx.x;     // 65536
    if (idx >= PROWS_*E_) return;
    float x = g_x[idx];
    float gl = 0.5f * x * (1.f + erff(x * 0.70710678118654752f));
    g_x[idx] = gl + g_res[idx];
}

// ---------------- outs = x @ Wc^T + bc (one warp per output) ----------------
__global__ void outs_k(const float* __restrict__ Wc, const float* __restrict__ bc)
{
    // 32 blocks x 8 warps = 256 warps; one warp per (row, j) output
    int warp = (blockIdx.x*256 + threadIdx.x) >> 5;
    int lane = threadIdx.x & 31;
    if (warp >= PROWS_*2) return;
    int row = warp >> 1, j = warp & 1;
    const float* xr = g_x + (size_t)row*E_;
    const float* wr = Wc + (size_t)j*E_;
    float s = 0.f;
    #pragma unroll
    for (int k = lane; k < E_; k += 32) s += xr[k]*wr[k];
    #pragma unroll
    for (int o = 16; o; o >>= 1) s += __shfl_xor_sync(0xffffffffu, s, o);
    if (lane == 0) g_outs[row*2 + j] = s + bc[j];
}

// ---------------- segment stats ----------------
__global__ void zero_stats_k()
{
    int t = threadIdx.x;
    if (t < B_*17*3) g_sums[t] = 0.f;
    if (t < B_*17)   g_cnt[t]  = 0.f;
}

__global__ void segsum_k(const float* __restrict__ probs, const int* __restrict__ masks)
{
    int b = blockIdx.x >> 4;
    int chunk = blockIdx.x & 15;
    __shared__ float s_sum[17*3];
    __shared__ float s_cnt[17];
    int t = threadIdx.x;            // 256
    if (t < 51) s_sum[t] = 0.f;
    if (t < 17) s_cnt[t] = 0.f;
    __syncthreads();
    const int* mrow = masks + (size_t)b*65536;
    const float* p0 = probs + (size_t)b*3*65536;
    int base = chunk*4096;
    for (int u = 0; u < 16; u++) {
        int pix = base + u*256 + t;
        int lab = mrow[pix];
        atomicAdd(&s_cnt[lab], 1.f);
        atomicAdd(&s_sum[lab*3 + 0], p0[pix]);
        atomicAdd(&s_sum[lab*3 + 1], p0[65536 + pix]);
        atomicAdd(&s_sum[lab*3 + 2], p0[131072 + pix]);
    }
    __syncthreads();
    if (t < 51) atomicAdd(&g_sums[b*51 + t], s_sum[t]);
    if (t < 17) atomicAdd(&g_cnt[b*17 + t],  s_cnt[t]);
}

__global__ void newv_k()
{
    int t = threadIdx.x;            // 128
    if (t >= 128) return;
    int b = t >> 4, p = t & 15;
    int lab = p + 1;
    float c = fmaxf(g_cnt[b*17 + lab], 1.f);
    float m0 = g_sums[b*51 + lab*3 + 0]/c + 1e-6f;
    float m1 = g_sums[b*51 + lab*3 + 1]/c + 1e-6f;
    float m2 = g_sums[b*51 + lab*3 + 2]/c + 1e-6f;
    int row = b*16 + p;
    float o0 = g_outs[row*2 + 0];
    float o1 = g_outs[row*2 + 1];
    float om = 0.5f*(o0 + o1);
    float new0 = m0 / (0.5f*(m1 + m2)) * om;
    g_newv[(b*17 + lab)*3 + 0] = new0;
    g_newv[(b*17 + lab)*3 + 1] = o0;
    g_newv[(b*17 + lab)*3 + 2] = o1;
    if (p == 0) {
        g_newv[(b*17)*3 + 0] = 0.f;
        g_newv[(b*17)*3 + 1] = 0.f;
        g_newv[(b*17)*3 + 2] = 0.f;
    }
}

// ---------------- final scatter ----------------
__global__ void scatter_k(const float* __restrict__ probs, const int* __restrict__ masks,
                          float* __restrict__ out)
{
    int idx = blockIdx.x*256 + threadIdx.x;     // 524288 pixels
    if (idx >= B_*65536) return;
    int b = idx >> 16;
    int pix = idx & 65535;
    int lab = masks[idx];
    float* o = out + (size_t)b*3*65536 + pix;
    if (lab > 0) {
        const float* v = &g_newv[(b*17 + lab)*3];
        o[0]      = v[0];
        o[65536]  = v[1];
        o[131072] = v[2];
    } else {
        const float* p = probs + (size_t)b*3*65536 + pix;
        o[0]      = p[0];
        o[65536]  = p[65536];
        o[131072] = p[131072];
    }
}

// ---------------- launch ----------------
static float* sym_addr(const void* symbol)
{
    void* p = nullptr;
    cudaGetSymbolAddress(&p, symbol);
    return (float*)p;
}

extern "C" void kernel_launch(void* const* d_in, const int* in_sizes, int n_in,
                              void* d_out, int out_size)
{
    const float* features = (const float*)d_in[0];
    const float* probs    = (const float*)d_in[1];
    const float* patches  = (const float*)d_in[2];
    const int*   masks    = (const int*)  d_in[3];
    const float* ln_g     = (const float*)d_in[4];
    const float* ln_b     = (const float*)d_in[5];
    const float* Wr       = (const float*)d_in[6];
    const float* br       = (const float*)d_in[7];
    const float* Wqkv     = (const float*)d_in[8];
    const float* bqkv     = (const float*)d_in[9];
    const float* Wo       = (const float*)d_in[10];
    const float* bo       = (const float*)d_in[11];
    const float* Wm       = (const float*)d_in[12];
    const float* bm       = (const float*)d_in[13];
    const float* Wc       = (const float*)d_in[14];
    const float* bc       = (const float*)d_in[15];
    float* out = (float*)d_out;

    float* emb   = sym_addr(g_emb);
    float* q     = sym_addr(g_q);
    float* kv    = sym_addr(g_kv);
    float* attn  = sym_addr(g_attn);
    float* attnp = sym_addr(g_attnp);
    float* res   = sym_addr(g_res);
    float* x     = sym_addr(g_x);

    // 1. pooling
    pool_features_k<<<(B_*16*128*128 + 255)/256, 256>>>(features);
    pool_patches_k<<<(PROWS_*FV_ + 255)/256, 256>>>(patches);

    // 2. embedding GEMM (fused block gather): [1928, 4096] x [512, 4096]^T
    gemm_tc_k<<<dim3(E_/64, (ROWS_ + 127)/128), 256>>>(nullptr, Wr, br, emb,
                                                       ROWS_, E_, FV_, 1);

    // 3. LayerNorm (in place)
    add_ln_k<<<ROWS_, 128>>>(emb, nullptr, ln_g, ln_b, emb);

    // 4. projections
    gemm_tc_k<<<dim3(E_/64, 1), 256>>>(emb, Wqkv, bqkv, q, PROWS_, E_, E_, 0);
    gemm_tc_k<<<dim3(2*E_/64, (BROWS_ + 127)/128), 256>>>(emb + (size_t)PROWS_*E_,
                                                          Wqkv + (size_t)E_*E_, bqkv + E_,
                                                          kv, BROWS_, 2*E_, E_, 0);

    // 5. attention
    attention_k<<<B_*HEADS_, 256>>>();

    // 6. output proj + residual LN
    gemm_tc_k<<<dim3(E_/64, 1), 256>>>(attn, Wo, bo, attnp, PROWS_, E_, E_, 0);
    add_ln_k<<<PROWS_, 128>>>(attnp, emb, ln_g, ln_b, res);

    // 7. MLP
    gemm_tc_k<<<dim3(E_/64, 1), 256>>>(res, Wm, bm, x, PROWS_, E_, E_, 0);
    gelu_add_k<<<(PROWS_*E_ + 255)/256, 256>>>();
    outs_k<<<32, 256>>>(Wc, bc);

    // 8. segment stats
    zero_stats_k<<<1, 512>>>();
    segsum_k<<<B_*16, 256>>>(probs, masks);
    newv_k<<<1, 128>>>();

    // 9. scatter
    scatter_k<<<(B_*65536 + 255)/256, 256>>>(probs, masks, out);
}